// round 15
// baseline (speedup 1.0000x reference)
#include <cuda_runtime.h>
#include <cuda_bf16.h>
#include <math.h>
#include <limits.h>

#define B     32
#define D     512
#define M     10000
#define KTOP  5
#define R3    32768
#define EPS   1e-12f

#define KPB   128           // keys per sim block (79 blocks)
#define KCH   128           // K-chunk in floats (4 chunks of 128)
// A smem rows padded: 128 bf16 -> 136 (272B rows; frag loads conflict-free)
#define AROW_BF   136
#define AROW_BYTES (AROW_BF * 2)            // 272
#define A_BYTES (KPB * AROW_BYTES)          // 34816
#define SIM_SMEM (2 * A_BYTES)              // 69632 (hi, lo)

typedef unsigned int u32;

// -------- device scratch --------
__device__ float g_sims[B * M];             // finished sim * rk (rq folded later)
__device__ float g_rk[M];
__device__ float g_rq[B];
__device__ u32   g_xhi[B * 256];            // x hi bf16 pairs [b][k/2]
__device__ u32   g_xlo[B * 256];            // x lo bf16 pairs
__device__ int   g_topidx[B * KTOP];
__device__ float g_topval[B * KTOP];

// ============================================================
// Kernel 0: x -> bf16 hi/lo pairs (u32 = 2 bf16 along k).
// ============================================================
__global__ void k_xcvt(const float* __restrict__ x) {
    int t = blockIdx.x * 256 + threadIdx.x;      // 4096 float4s
    float4 v = ((const float4*)x)[t];
    __nv_bfloat162 h01 = __floats2bfloat162_rn(v.x, v.y);
    __nv_bfloat162 h23 = __floats2bfloat162_rn(v.z, v.w);
    g_xhi[2 * t]     = *(u32*)&h01;
    g_xhi[2 * t + 1] = *(u32*)&h23;
    __nv_bfloat162 l01 = __floats2bfloat162_rn(v.x - __low2float(h01), v.y - __high2float(h01));
    __nv_bfloat162 l23 = __floats2bfloat162_rn(v.z - __low2float(h23), v.w - __high2float(h23));
    g_xlo[2 * t]     = *(u32*)&l01;
    g_xlo[2 * t + 1] = *(u32*)&l23;
}

// ============================================================
// Kernel 1: norms, warp per row. 1254 blocks x 8 warps = 10032 rows.
// ============================================================
__global__ void __launch_bounds__(256) k_nrm(const float* __restrict__ x,
                                             const float* __restrict__ keys) {
    const int gw   = blockIdx.x * 8 + (threadIdx.x >> 5);
    const int lane = threadIdx.x & 31;
    const float4* src;
    if (gw < M)            src = (const float4*)keys + (size_t)gw * 128;
    else if (gw < M + B)   src = (const float4*)x + (size_t)(gw - M) * 128;
    else return;

    float s = 0.f;
    #pragma unroll
    for (int j = 0; j < 4; ++j) {
        float4 v = src[lane + 32 * j];
        s += v.x * v.x + v.y * v.y + v.z * v.z + v.w * v.w;
    }
    #pragma unroll
    for (int o = 16; o > 0; o >>= 1) s += __shfl_xor_sync(0xFFFFFFFFu, s, o);
    if (lane == 0) {
        float r = 1.0f / fmaxf(sqrtf(s), EPS);
        if (gw < M) g_rk[gw] = r;
        else        g_rq[gw - M] = r;
    }
}

// ============================================================
// Kernel 2: similarity via mma.sync bf16 hi/lo, FULL K per block.
// grid 79, block 256 (8 warps). Block: 128 keys x 32 b x K=512.
// Warp w: m16 tile rows [w*16, w*16+16) x 32 b (4 n8 tiles).
// K processed in 4 chunks of 128 floats through smem; acc persists.
// Epilogue folds rk[m] -> writes finished g_sims.
// ============================================================
__global__ void __launch_bounds__(256) k_sim(const float* __restrict__ keys) {
    extern __shared__ char smem[];
    char* Ahi = smem;
    char* Alo = smem + A_BYTES;

    const int tid  = threadIdx.x;
    const int lane = tid & 31;
    const int w    = tid >> 5;          // 0..7 -> m16 tile
    const int gid  = lane >> 2;         // 0..7
    const int tg   = lane & 3;          // 0..3
    const int m0   = blockIdx.x * KPB;

    float acc[4][4];                     // [n8 tile][frag]
    #pragma unroll
    for (int jn = 0; jn < 4; ++jn)
        #pragma unroll
        for (int q = 0; q < 4; ++q) acc[jn][q] = 0.f;

    const u32* __restrict__ xhi = g_xhi;
    const u32* __restrict__ xlo = g_xlo;
    const float4* __restrict__ k4 = (const float4*)keys;

    #pragma unroll 1
    for (int kc = 0; kc < 4; ++kc) {     // K chunks of 128 floats (32 f4)
        __syncthreads();                 // protect smem reuse across chunks

        // ---- fill + convert keys: 128 rows x 32 f4 ----
        {
            const int c4   = tid & 31;
            const int row0 = tid >> 5;   // 0..7
            #pragma unroll
            for (int i = 0; i < 16; ++i) {
                int r  = row0 + 8 * i;
                int gm = m0 + r;
                float4 v = (gm < M) ? k4[(size_t)gm * 128 + kc * 32 + c4]
                                    : make_float4(0.f, 0.f, 0.f, 0.f);
                __nv_bfloat162 h01 = __floats2bfloat162_rn(v.x, v.y);
                __nv_bfloat162 h23 = __floats2bfloat162_rn(v.z, v.w);
                __nv_bfloat162 l01 = __floats2bfloat162_rn(v.x - __low2float(h01),
                                                           v.y - __high2float(h01));
                __nv_bfloat162 l23 = __floats2bfloat162_rn(v.z - __low2float(h23),
                                                           v.w - __high2float(h23));
                int off = r * AROW_BYTES + c4 * 8;
                *(uint2*)(Ahi + off) = make_uint2(*(u32*)&h01, *(u32*)&h23);
                *(uint2*)(Alo + off) = make_uint2(*(u32*)&l01, *(u32*)&l23);
            }
        }
        __syncthreads();

        // ---- mma: 8 k16 steps over this chunk ----
        #pragma unroll
        for (int ks = 0; ks < 8; ++ks) {
            u32 ah[4], al[4];
            {
                int r0  = w * 16 + gid;
                int byt = ks * 32 + tg * 4;
                ah[0] = *(const u32*)(Ahi + r0 * AROW_BYTES + byt);
                ah[1] = *(const u32*)(Ahi + (r0 + 8) * AROW_BYTES + byt);
                ah[2] = *(const u32*)(Ahi + r0 * AROW_BYTES + byt + 16);
                ah[3] = *(const u32*)(Ahi + (r0 + 8) * AROW_BYTES + byt + 16);
                al[0] = *(const u32*)(Alo + r0 * AROW_BYTES + byt);
                al[1] = *(const u32*)(Alo + (r0 + 8) * AROW_BYTES + byt);
                al[2] = *(const u32*)(Alo + r0 * AROW_BYTES + byt + 16);
                al[3] = *(const u32*)(Alo + (r0 + 8) * AROW_BYTES + byt + 16);
            }
            #pragma unroll
            for (int jn = 0; jn < 4; ++jn) {
                int n  = jn * 8 + gid;                   // b index
                int ki = kc * 64 + ks * 8 + tg;          // u32 index along k
                u32 bh0 = xhi[n * 256 + ki];
                u32 bh1 = xhi[n * 256 + ki + 4];
                u32 bl0 = xlo[n * 256 + ki];
                u32 bl1 = xlo[n * 256 + ki + 4];
                float* d = acc[jn];
                asm volatile(
                    "mma.sync.aligned.m16n8k16.row.col.f32.bf16.bf16.f32 "
                    "{%0,%1,%2,%3}, {%4,%5,%6,%7}, {%8,%9}, {%0,%1,%2,%3};"
                    : "+f"(d[0]), "+f"(d[1]), "+f"(d[2]), "+f"(d[3])
                    : "r"(ah[0]), "r"(ah[1]), "r"(ah[2]), "r"(ah[3]),
                      "r"(bh0), "r"(bh1));
                asm volatile(
                    "mma.sync.aligned.m16n8k16.row.col.f32.bf16.bf16.f32 "
                    "{%0,%1,%2,%3}, {%4,%5,%6,%7}, {%8,%9}, {%0,%1,%2,%3};"
                    : "+f"(d[0]), "+f"(d[1]), "+f"(d[2]), "+f"(d[3])
                    : "r"(ah[0]), "r"(ah[1]), "r"(ah[2]), "r"(ah[3]),
                      "r"(bl0), "r"(bl1));
                asm volatile(
                    "mma.sync.aligned.m16n8k16.row.col.f32.bf16.bf16.f32 "
                    "{%0,%1,%2,%3}, {%4,%5,%6,%7}, {%8,%9}, {%0,%1,%2,%3};"
                    : "+f"(d[0]), "+f"(d[1]), "+f"(d[2]), "+f"(d[3])
                    : "r"(al[0]), "r"(al[1]), "r"(al[2]), "r"(al[3]),
                      "r"(bh0), "r"(bh1));
            }
        }
    }

    // ---- epilogue: fold rk, write finished sims ----
    {
        int m1 = m0 + w * 16 + gid;
        int m2 = m1 + 8;
        float rk1 = (m1 < M) ? g_rk[m1] : 0.f;
        float rk2 = (m2 < M) ? g_rk[m2] : 0.f;
        #pragma unroll
        for (int jn = 0; jn < 4; ++jn) {
            int b1 = jn * 8 + 2 * tg;
            if (m1 < M) {
                g_sims[b1 * M + m1]       = acc[jn][0] * rk1;
                g_sims[(b1 + 1) * M + m1] = acc[jn][1] * rk1;
            }
            if (m2 < M) {
                g_sims[b1 * M + m2]       = acc[jn][2] * rk2;
                g_sims[(b1 + 1) * M + m2] = acc[jn][3] * rk2;
            }
        }
    }
}

// ============================================================
// Kernel 3: top-5 over a single finished array. 32 blocks x 256.
// Tie-break: lower index (matches jax.lax.top_k).
// ============================================================
#define INS5(v, m)                                                                 \
    if ((v) > t4) {                                                                \
        if ((v) > t0)      { t4=t3;x4=x3; t3=t2;x3=x2; t2=t1;x2=x1; t1=t0;x1=x0; t0=(v);x0=(m); } \
        else if ((v) > t1) { t4=t3;x4=x3; t3=t2;x3=x2; t2=t1;x2=x1; t1=(v);x1=(m); }              \
        else if ((v) > t2) { t4=t3;x4=x3; t3=t2;x3=x2; t2=(v);x2=(m); }                            \
        else if ((v) > t3) { t4=t3;x4=x3; t3=(v);x3=(m); }                                         \
        else               { t4=(v);x4=(m); }                                                      \
    }

__global__ void __launch_bounds__(256) k_topk() {
    __shared__ float s_cv[40];
    __shared__ int   s_ci[40];

    const int b    = blockIdx.x;
    const int tid  = threadIdx.x;
    const int w    = tid >> 5;
    const int lane = tid & 31;

    const float4* __restrict__ sp = (const float4*)(g_sims + b * M);

    float t0 = -INFINITY, t1 = -INFINITY, t2 = -INFINITY, t3 = -INFINITY, t4 = -INFINITY;
    int   x0 = INT_MAX, x1 = INT_MAX, x2 = INT_MAX, x3 = INT_MAX, x4 = INT_MAX;

    #pragma unroll 2
    for (int it = 0; it < 10; ++it) {
        int m4 = tid + 256 * it;
        if (m4 < 2500) {
            float4 v = sp[m4];
            int m = 4 * m4;
            INS5(v.x, m)
            INS5(v.y, m + 1)
            INS5(v.z, m + 2)
            INS5(v.w, m + 3)
        }
    }

    #pragma unroll
    for (int kk = 0; kk < 5; ++kk) {
        float bv = t0; int bi = x0;
        #pragma unroll
        for (int o = 16; o > 0; o >>= 1) {
            float ov = __shfl_xor_sync(0xFFFFFFFFu, bv, o);
            int   oi = __shfl_xor_sync(0xFFFFFFFFu, bi, o);
            if (ov > bv || (ov == bv && oi < bi)) { bv = ov; bi = oi; }
        }
        if (x0 == bi) { t0=t1;x0=x1; t1=t2;x1=x2; t2=t3;x2=x3; t3=t4;x3=x4; t4=-INFINITY;x4=INT_MAX; }
        if (lane == 0) { s_cv[w * 5 + kk] = bv; s_ci[w * 5 + kk] = bi; }
    }
    __syncthreads();

    if (w == 0) {
        float rq = g_rq[b];
        float va = s_cv[lane];
        int   ia = s_ci[lane];
        float vb = (lane + 32 < 40) ? s_cv[lane + 32] : -INFINITY;
        int   ib = (lane + 32 < 40) ? s_ci[lane + 32] : INT_MAX;
        if (vb > va || (vb == va && ib < ia)) {
            float tv = va; va = vb; vb = tv;
            int   ti = ia; ia = ib; ib = ti;
        }
        #pragma unroll
        for (int kk = 0; kk < 5; ++kk) {
            float bv = va; int bi = ia;
            #pragma unroll
            for (int o = 16; o > 0; o >>= 1) {
                float ov = __shfl_xor_sync(0xFFFFFFFFu, bv, o);
                int   oi = __shfl_xor_sync(0xFFFFFFFFu, bi, o);
                if (ov > bv || (ov == bv && oi < bi)) { bv = ov; bi = oi; }
            }
            if (ia == bi) { va = vb; ia = ib; vb = -INFINITY; ib = INT_MAX; }
            if (lane == 0) { g_topval[b * KTOP + kk] = bv * rq; g_topidx[b * KTOP + kk] = bi; }
        }
    }
}

// ============================================================
// Kernel 4: gather. 640 blocks x 32KB, batched MLP=8 (measured best).
// ============================================================
__global__ void __launch_bounds__(256) k_gather(const float* __restrict__ vals,
                                                float* __restrict__ out,
                                                int out_size) {
    const int pair  = blockIdx.x >> 2;   // 0..159
    const int chunk = blockIdx.x & 3;    // 0..3
    const int t     = threadIdx.x;

    const int idx = g_topidx[pair];
    const float4* __restrict__ src = (const float4*)vals + (size_t)idx  * 8192 + chunk * 2048;
    float4*       __restrict__ dst = (float4*)out        + (size_t)pair * 8192 + chunk * 2048;

    float4 tmp[8];
    #pragma unroll
    for (int i = 0; i < 8; ++i) tmp[i] = __ldcs(src + t + 256 * i);
    #pragma unroll
    for (int i = 0; i < 8; ++i) __stcs(dst + t + 256 * i, tmp[i]);

    if (blockIdx.x == 0) {
        const int total = B * KTOP * R3;   // 5242880
        if (out_size >= total + 2 * B * KTOP && t < B * KTOP) {
            out[total + t]            = (float)g_topidx[t];
            out[total + B * KTOP + t] = g_topval[t];
        }
    }
}

// ============================================================
extern "C" void kernel_launch(void* const* d_in, const int* in_sizes, int n_in,
                              void* d_out, int out_size) {
    const float* x    = (const float*)d_in[0];  // (32, 512)
    const float* keys = (const float*)d_in[1];  // (10000, 512)
    const float* vals = (const float*)d_in[2];  // (10000, 32, 32, 32)

    float* out = (float*)d_out;

    cudaFuncSetAttribute(k_sim, cudaFuncAttributeMaxDynamicSharedMemorySize, SIM_SMEM);

    k_xcvt<<<16, 256>>>(x);
    k_nrm<<<1254, 256>>>(x, keys);
    k_sim<<<79, 256, SIM_SMEM>>>(keys);
    k_topk<<<B, 256>>>();
    k_gather<<<B * KTOP * 4, 256>>>(vals, out, out_size);
}

// round 16
// speedup vs baseline: 1.1405x; 1.1405x over previous
#include <cuda_runtime.h>
#include <cuda_bf16.h>
#include <math.h>
#include <limits.h>

#define B     32
#define D     512
#define M     10000
#define KTOP  5
#define R3    32768
#define EPS   1e-12f

#define KPB   128           // keys per sim block
#define AROW_BF   136       // padded row: 128 bf16 -> 136
#define AROW_BYTES (AROW_BF * 2)            // 272
#define A_BYTES (KPB * AROW_BYTES)          // 34816
#define SIM_SMEM (2 * A_BYTES)              // 69632 (hi, lo)

#define NSEG  5             // topk phase-1 segments per row (2000 elems each)

typedef unsigned int u32;

// -------- device scratch --------
__device__ float g_spart2[2][B * M];        // rk-folded partial sims per K-half
__device__ float g_rk[M];
__device__ float g_rq[B];
__device__ u32   g_xhi[B * 256];            // x hi bf16 pairs [b][k/2]
__device__ u32   g_xlo[B * 256];            // x lo bf16 pairs
__device__ float g_cand_v[B * NSEG * KTOP];
__device__ int   g_cand_i[B * NSEG * KTOP];
__device__ int   g_topidx[B * KTOP];
__device__ float g_topval[B * KTOP];

// ============================================================
// Kernel 0: x -> bf16 hi/lo pairs (u32 = 2 bf16 along k).
// ============================================================
__global__ void k_xcvt(const float* __restrict__ x) {
    int t = blockIdx.x * 256 + threadIdx.x;      // 4096 float4s
    float4 v = ((const float4*)x)[t];
    __nv_bfloat162 h01 = __floats2bfloat162_rn(v.x, v.y);
    __nv_bfloat162 h23 = __floats2bfloat162_rn(v.z, v.w);
    g_xhi[2 * t]     = *(u32*)&h01;
    g_xhi[2 * t + 1] = *(u32*)&h23;
    __nv_bfloat162 l01 = __floats2bfloat162_rn(v.x - __low2float(h01), v.y - __high2float(h01));
    __nv_bfloat162 l23 = __floats2bfloat162_rn(v.z - __low2float(h23), v.w - __high2float(h23));
    g_xlo[2 * t]     = *(u32*)&l01;
    g_xlo[2 * t + 1] = *(u32*)&l23;
}

// ============================================================
// Kernel 1: norms, warp per row. 1254 blocks x 8 warps = 10032 rows.
// ============================================================
__global__ void __launch_bounds__(256) k_nrm(const float* __restrict__ x,
                                             const float* __restrict__ keys) {
    const int gw   = blockIdx.x * 8 + (threadIdx.x >> 5);
    const int lane = threadIdx.x & 31;
    const float4* src;
    if (gw < M)            src = (const float4*)keys + (size_t)gw * 128;
    else if (gw < M + B)   src = (const float4*)x + (size_t)(gw - M) * 128;
    else return;

    float s = 0.f;
    #pragma unroll
    for (int j = 0; j < 4; ++j) {
        float4 v = src[lane + 32 * j];
        s += v.x * v.x + v.y * v.y + v.z * v.z + v.w * v.w;
    }
    #pragma unroll
    for (int o = 16; o > 0; o >>= 1) s += __shfl_xor_sync(0xFFFFFFFFu, s, o);
    if (lane == 0) {
        float r = 1.0f / fmaxf(sqrtf(s), EPS);
        if (gw < M) g_rk[gw] = r;
        else        g_rq[gw - M] = r;
    }
}

// ============================================================
// Kernel 2: similarity via mma.sync bf16 hi/lo. grid (79, 2).
// Block: 128 keys x 32 b x 256-float K-half (2 smem chunks).
// Warp w: m16 tile rows [w*16, w*16+16) x 32 b (4 n8 tiles).
// Epilogue folds rk -> writes rk-scaled partial to g_spart2[kh].
// ============================================================
__global__ void __launch_bounds__(256) k_sim(const float* __restrict__ keys) {
    extern __shared__ char smem[];
    char* Ahi = smem;
    char* Alo = smem + A_BYTES;

    const int tid  = threadIdx.x;
    const int lane = tid & 31;
    const int w    = tid >> 5;          // 0..7 -> m16 tile
    const int gid  = lane >> 2;         // 0..7
    const int tg   = lane & 3;          // 0..3
    const int m0   = blockIdx.x * KPB;
    const int kh   = blockIdx.y;        // K-half

    float acc[4][4];
    #pragma unroll
    for (int jn = 0; jn < 4; ++jn)
        #pragma unroll
        for (int q = 0; q < 4; ++q) acc[jn][q] = 0.f;

    const u32* __restrict__ xhi = g_xhi;
    const u32* __restrict__ xlo = g_xlo;
    const float4* __restrict__ k4 = (const float4*)keys;

    #pragma unroll 1
    for (int kc = 0; kc < 2; ++kc) {     // 2 chunks of 128 floats
        const int gkc = kh * 2 + kc;     // global chunk 0..3
        __syncthreads();

        // ---- fill + convert keys: 128 rows x 32 f4 ----
        {
            const int c4   = tid & 31;
            const int row0 = tid >> 5;   // 0..7
            #pragma unroll
            for (int i = 0; i < 16; ++i) {
                int r  = row0 + 8 * i;
                int gm = m0 + r;
                float4 v = (gm < M) ? k4[(size_t)gm * 128 + gkc * 32 + c4]
                                    : make_float4(0.f, 0.f, 0.f, 0.f);
                __nv_bfloat162 h01 = __floats2bfloat162_rn(v.x, v.y);
                __nv_bfloat162 h23 = __floats2bfloat162_rn(v.z, v.w);
                __nv_bfloat162 l01 = __floats2bfloat162_rn(v.x - __low2float(h01),
                                                           v.y - __high2float(h01));
                __nv_bfloat162 l23 = __floats2bfloat162_rn(v.z - __low2float(h23),
                                                           v.w - __high2float(h23));
                int off = r * AROW_BYTES + c4 * 8;
                *(uint2*)(Ahi + off) = make_uint2(*(u32*)&h01, *(u32*)&h23);
                *(uint2*)(Alo + off) = make_uint2(*(u32*)&l01, *(u32*)&l23);
            }
        }
        __syncthreads();

        // ---- mma: 8 k16 steps over this chunk ----
        #pragma unroll
        for (int ks = 0; ks < 8; ++ks) {
            u32 ah[4], al[4];
            {
                int r0  = w * 16 + gid;
                int byt = ks * 32 + tg * 4;
                ah[0] = *(const u32*)(Ahi + r0 * AROW_BYTES + byt);
                ah[1] = *(const u32*)(Ahi + (r0 + 8) * AROW_BYTES + byt);
                ah[2] = *(const u32*)(Ahi + r0 * AROW_BYTES + byt + 16);
                ah[3] = *(const u32*)(Ahi + (r0 + 8) * AROW_BYTES + byt + 16);
                al[0] = *(const u32*)(Alo + r0 * AROW_BYTES + byt);
                al[1] = *(const u32*)(Alo + (r0 + 8) * AROW_BYTES + byt);
                al[2] = *(const u32*)(Alo + r0 * AROW_BYTES + byt + 16);
                al[3] = *(const u32*)(Alo + (r0 + 8) * AROW_BYTES + byt + 16);
            }
            #pragma unroll
            for (int jn = 0; jn < 4; ++jn) {
                int n  = jn * 8 + gid;                   // b index
                int ki = gkc * 64 + ks * 8 + tg;         // u32 index along k
                u32 bh0 = xhi[n * 256 + ki];
                u32 bh1 = xhi[n * 256 + ki + 4];
                u32 bl0 = xlo[n * 256 + ki];
                u32 bl1 = xlo[n * 256 + ki + 4];
                float* d = acc[jn];
                asm volatile(
                    "mma.sync.aligned.m16n8k16.row.col.f32.bf16.bf16.f32 "
                    "{%0,%1,%2,%3}, {%4,%5,%6,%7}, {%8,%9}, {%0,%1,%2,%3};"
                    : "+f"(d[0]), "+f"(d[1]), "+f"(d[2]), "+f"(d[3])
                    : "r"(ah[0]), "r"(ah[1]), "r"(ah[2]), "r"(ah[3]),
                      "r"(bh0), "r"(bh1));
                asm volatile(
                    "mma.sync.aligned.m16n8k16.row.col.f32.bf16.bf16.f32 "
                    "{%0,%1,%2,%3}, {%4,%5,%6,%7}, {%8,%9}, {%0,%1,%2,%3};"
                    : "+f"(d[0]), "+f"(d[1]), "+f"(d[2]), "+f"(d[3])
                    : "r"(ah[0]), "r"(ah[1]), "r"(ah[2]), "r"(ah[3]),
                      "r"(bl0), "r"(bl1));
                asm volatile(
                    "mma.sync.aligned.m16n8k16.row.col.f32.bf16.bf16.f32 "
                    "{%0,%1,%2,%3}, {%4,%5,%6,%7}, {%8,%9}, {%0,%1,%2,%3};"
                    : "+f"(d[0]), "+f"(d[1]), "+f"(d[2]), "+f"(d[3])
                    : "r"(al[0]), "r"(al[1]), "r"(al[2]), "r"(al[3]),
                      "r"(bh0), "r"(bh1));
            }
        }
    }

    // ---- epilogue: fold rk, write rk-scaled partial ----
    {
        int m1 = m0 + w * 16 + gid;
        int m2 = m1 + 8;
        float rk1 = (m1 < M) ? g_rk[m1] : 0.f;
        float rk2 = (m2 < M) ? g_rk[m2] : 0.f;
        #pragma unroll
        for (int jn = 0; jn < 4; ++jn) {
            int b1 = jn * 8 + 2 * tg;
            if (m1 < M) {
                g_spart2[kh][b1 * M + m1]       = acc[jn][0] * rk1;
                g_spart2[kh][(b1 + 1) * M + m1] = acc[jn][1] * rk1;
            }
            if (m2 < M) {
                g_spart2[kh][b1 * M + m2]       = acc[jn][2] * rk2;
                g_spart2[kh][(b1 + 1) * M + m2] = acc[jn][3] * rk2;
            }
        }
    }
}

// ============================================================
// Kernel 3a: topk phase 1. grid (32, 5) = 160 blocks x 256.
// Block (b, seg): top-5 of elements [seg*2000, seg*2000+2000).
// Tie-break: lower index.
// ============================================================
#define INS5(v, m)                                                                 \
    if ((v) > t4) {                                                                \
        if ((v) > t0)      { t4=t3;x4=x3; t3=t2;x3=x2; t2=t1;x2=x1; t1=t0;x1=x0; t0=(v);x0=(m); } \
        else if ((v) > t1) { t4=t3;x4=x3; t3=t2;x3=x2; t2=t1;x2=x1; t1=(v);x1=(m); }              \
        else if ((v) > t2) { t4=t3;x4=x3; t3=t2;x3=x2; t2=(v);x2=(m); }                            \
        else if ((v) > t3) { t4=t3;x4=x3; t3=(v);x3=(m); }                                         \
        else               { t4=(v);x4=(m); }                                                      \
    }

__global__ void __launch_bounds__(256) k_top1() {
    __shared__ float s_cv[40];
    __shared__ int   s_ci[40];

    const int b    = blockIdx.x;
    const int seg  = blockIdx.y;
    const int tid  = threadIdx.x;
    const int w    = tid >> 5;
    const int lane = tid & 31;

    const float4* __restrict__ sp0 = (const float4*)(g_spart2[0] + b * M);
    const float4* __restrict__ sp1 = (const float4*)(g_spart2[1] + b * M);

    float t0 = -INFINITY, t1 = -INFINITY, t2 = -INFINITY, t3 = -INFINITY, t4 = -INFINITY;
    int   x0 = INT_MAX, x1 = INT_MAX, x2 = INT_MAX, x3 = INT_MAX, x4 = INT_MAX;

    #pragma unroll
    for (int it = 0; it < 2; ++it) {
        int off = tid + 256 * it;                 // 0..511
        if (off < 500) {
            int m4 = seg * 500 + off;             // f4 index in row
            float4 a = sp0[m4], c = sp1[m4];
            int m = 4 * m4;
            INS5(a.x + c.x, m)
            INS5(a.y + c.y, m + 1)
            INS5(a.z + c.z, m + 2)
            INS5(a.w + c.w, m + 3)
        }
    }

    #pragma unroll
    for (int kk = 0; kk < 5; ++kk) {
        float bv = t0; int bi = x0;
        #pragma unroll
        for (int o = 16; o > 0; o >>= 1) {
            float ov = __shfl_xor_sync(0xFFFFFFFFu, bv, o);
            int   oi = __shfl_xor_sync(0xFFFFFFFFu, bi, o);
            if (ov > bv || (ov == bv && oi < bi)) { bv = ov; bi = oi; }
        }
        if (x0 == bi) { t0=t1;x0=x1; t1=t2;x1=x2; t2=t3;x2=x3; t3=t4;x3=x4; t4=-INFINITY;x4=INT_MAX; }
        if (lane == 0) { s_cv[w * 5 + kk] = bv; s_ci[w * 5 + kk] = bi; }
    }
    __syncthreads();

    if (w == 0) {
        float va = s_cv[lane];
        int   ia = s_ci[lane];
        float vb = (lane + 32 < 40) ? s_cv[lane + 32] : -INFINITY;
        int   ib = (lane + 32 < 40) ? s_ci[lane + 32] : INT_MAX;
        if (vb > va || (vb == va && ib < ia)) {
            float tv = va; va = vb; vb = tv;
            int   ti = ia; ia = ib; ib = ti;
        }
        #pragma unroll
        for (int kk = 0; kk < 5; ++kk) {
            float bv = va; int bi = ia;
            #pragma unroll
            for (int o = 16; o > 0; o >>= 1) {
                float ov = __shfl_xor_sync(0xFFFFFFFFu, bv, o);
                int   oi = __shfl_xor_sync(0xFFFFFFFFu, bi, o);
                if (ov > bv || (ov == bv && oi < bi)) { bv = ov; bi = oi; }
            }
            if (ia == bi) { va = vb; ia = ib; vb = -INFINITY; ib = INT_MAX; }
            if (lane == 0) {
                g_cand_v[(b * NSEG + seg) * KTOP + kk] = bv;
                g_cand_i[(b * NSEG + seg) * KTOP + kk] = bi;
            }
        }
    }
}

// ============================================================
// Kernel 3b: topk phase 2. 32 blocks x 32 threads.
// Merge 25 candidates per row; apply rq to outputs.
// ============================================================
__global__ void __launch_bounds__(32) k_top2() {
    const int b    = blockIdx.x;
    const int lane = threadIdx.x;

    float va = (lane < NSEG * KTOP) ? g_cand_v[b * NSEG * KTOP + lane] : -INFINITY;
    int   ia = (lane < NSEG * KTOP) ? g_cand_i[b * NSEG * KTOP + lane] : INT_MAX;
    const float rq = g_rq[b];

    #pragma unroll
    for (int kk = 0; kk < 5; ++kk) {
        float bv = va; int bi = ia;
        #pragma unroll
        for (int o = 16; o > 0; o >>= 1) {
            float ov = __shfl_xor_sync(0xFFFFFFFFu, bv, o);
            int   oi = __shfl_xor_sync(0xFFFFFFFFu, bi, o);
            if (ov > bv || (ov == bv && oi < bi)) { bv = ov; bi = oi; }
        }
        if (ia == bi) { va = -INFINITY; ia = INT_MAX; }
        if (lane == 0) {
            g_topval[b * KTOP + kk] = bv * rq;
            g_topidx[b * KTOP + kk] = bi;
        }
    }
}

// ============================================================
// Kernel 4: gather. 640 blocks x 32KB, batched MLP=8 (measured best).
// ============================================================
__global__ void __launch_bounds__(256) k_gather(const float* __restrict__ vals,
                                                float* __restrict__ out,
                                                int out_size) {
    const int pair  = blockIdx.x >> 2;   // 0..159
    const int chunk = blockIdx.x & 3;    // 0..3
    const int t     = threadIdx.x;

    const int idx = g_topidx[pair];
    const float4* __restrict__ src = (const float4*)vals + (size_t)idx  * 8192 + chunk * 2048;
    float4*       __restrict__ dst = (float4*)out        + (size_t)pair * 8192 + chunk * 2048;

    float4 tmp[8];
    #pragma unroll
    for (int i = 0; i < 8; ++i) tmp[i] = __ldcs(src + t + 256 * i);
    #pragma unroll
    for (int i = 0; i < 8; ++i) __stcs(dst + t + 256 * i, tmp[i]);

    if (blockIdx.x == 0) {
        const int total = B * KTOP * R3;   // 5242880
        if (out_size >= total + 2 * B * KTOP && t < B * KTOP) {
            out[total + t]            = (float)g_topidx[t];
            out[total + B * KTOP + t] = g_topval[t];
        }
    }
}

// ============================================================
extern "C" void kernel_launch(void* const* d_in, const int* in_sizes, int n_in,
                              void* d_out, int out_size) {
    const float* x    = (const float*)d_in[0];  // (32, 512)
    const float* keys = (const float*)d_in[1];  // (10000, 512)
    const float* vals = (const float*)d_in[2];  // (10000, 32, 32, 32)

    float* out = (float*)d_out;

    cudaFuncSetAttribute(k_sim, cudaFuncAttributeMaxDynamicSharedMemorySize, SIM_SMEM);

    k_xcvt<<<16, 256>>>(x);
    k_nrm<<<1254, 256>>>(x, keys);
    k_sim<<<dim3(79, 2), 256, SIM_SMEM>>>(keys);   // 158 blocks
    k_top1<<<dim3(B, NSEG), 256>>>();              // 160 blocks
    k_top2<<<B, 32>>>();
    k_gather<<<B * KTOP * 4, 256>>>(vals, out, out_size);
}